// round 4
// baseline (speedup 1.0000x reference)
#include <cuda_runtime.h>
#include <math.h>

#define NV       2000000
#define NGROUPS  (NV/4)                 // 500000 groups of 4 vertices
#define BLOCK    256
#define NBP      444                    // persistent grid: 3 blocks/SM x 148 SMs
#define TSTEPS   240
#define STRIDE   (NBP*BLOCK)

#define F_DT     (1.0f/600.0f)
#define F_NX     (-0.34202014332566871291f)
#define F_NY     ( 0.93969262078590838405f)
#define F_THR    (-0.093969262078590838405f)   // -cos(slope)*0.1
#define F_EPS    1e-6f
#define F_INVM   (1.0f/2000000.0f)

// ---------------- device state ----------------
__device__ double  g_I6[6];              // fp64 sums: xx,yy,zz,xy,xz,yz
__device__ float   g_If[9];              // body-frame inertia (fp32, row-major) — const during persist
__device__ float   g_S[13];              // trans[0..2], quat[3..6], v[7..9], omega[10..12]
__device__ float   g_pre[18];            // precomputed R[0..8], Iinv[9..17] for current quat
__device__ float   g_mcf[3];
__device__ float   g_kn, g_mu, g_ld, g_ad;
__device__ float   g_AB[8];              // Ax,Ay,Az,thrA, Bx,By,Bz,thrB
__device__ float   g_sum[3];
__device__ int     g_cnt;
__device__ unsigned g_arrive;
__device__ unsigned g_release;           // number of completed steps

// ---------------- fp32 small math ----------------
__device__ __forceinline__ void quat_to_mat_f(float qw, float qx, float qy, float qz, float R[3][3]) {
    float n2 = qw*qw + qx*qx + qy*qy + qz*qz;
    float inv = 1.0f / sqrtf(n2);
    float w = qw*inv, x = qx*inv, y = qy*inv, z = qz*inv;
    R[0][0] = 1.0f - 2.0f*(y*y + z*z); R[0][1] = 2.0f*(x*y - w*z);        R[0][2] = 2.0f*(x*z + w*y);
    R[1][0] = 2.0f*(x*y + w*z);        R[1][1] = 1.0f - 2.0f*(x*x + z*z); R[1][2] = 2.0f*(y*z - w*x);
    R[2][0] = 2.0f*(x*z - w*y);        R[2][1] = 2.0f*(y*z + w*x);        R[2][2] = 1.0f - 2.0f*(x*x + y*y);
}

__device__ __forceinline__ void inv3f(const float m[3][3], float o[3][3]) {
    float c00 = m[1][1]*m[2][2] - m[1][2]*m[2][1];
    float c01 = m[1][2]*m[2][0] - m[1][0]*m[2][2];
    float c02 = m[1][0]*m[2][1] - m[1][1]*m[2][0];
    float det = m[0][0]*c00 + m[0][1]*c01 + m[0][2]*c02;
    float id = 1.0f/det;
    o[0][0] = c00*id;
    o[0][1] = (m[0][2]*m[2][1] - m[0][1]*m[2][2])*id;
    o[0][2] = (m[0][1]*m[1][2] - m[0][2]*m[1][1])*id;
    o[1][0] = c01*id;
    o[1][1] = (m[0][0]*m[2][2] - m[0][2]*m[2][0])*id;
    o[1][2] = (m[0][2]*m[1][0] - m[0][0]*m[1][2])*id;
    o[2][0] = c02*id;
    o[2][1] = (m[0][1]*m[2][0] - m[0][0]*m[2][1])*id;
    o[2][2] = (m[0][0]*m[1][1] - m[0][1]*m[1][0])*id;
}

__device__ __forceinline__ void mm3f(const float a[3][3], const float b[3][3], float c[3][3]) {
    #pragma unroll
    for (int i = 0; i < 3; i++)
        #pragma unroll
        for (int j = 0; j < 3; j++)
            c[i][j] = a[i][0]*b[0][j] + a[i][1]*b[1][j] + a[i][2]*b[2][j];
}

// store R and Iinv(R) for a given (normalized) R into g_pre
__device__ __forceinline__ void store_precomp(const float R[3][3]) {
    volatile float* P = g_pre;
    float In[3][3] = {{g_If[0], g_If[1], g_If[2]},
                      {g_If[3], g_If[4], g_If[5]},
                      {g_If[6], g_If[7], g_If[8]}};
    float Tm[3][3], Rt[3][3], Iw[3][3], Iinv[3][3];
    mm3f(R, In, Tm);
    #pragma unroll
    for (int i = 0; i < 3; i++)
        #pragma unroll
        for (int j = 0; j < 3; j++) Rt[i][j] = R[j][i];
    mm3f(Tm, Rt, Iw);
    inv3f(Iw, Iinv);
    #pragma unroll
    for (int i = 0; i < 3; i++)
        #pragma unroll
        for (int j = 0; j < 3; j++) { P[3*i+j] = R[i][j]; P[9 + 3*i+j] = Iinv[i][j]; }
}

// publish AB constants for the NEXT step, given new state (registers)
__device__ __forceinline__ void publish_AB(const float Rn[3][3],
                                           float tx, float ty,
                                           float vx, float vy,
                                           float wx, float wy, float wz) {
    volatile float* AB = g_AB;
    float Ax = Rn[0][0]*F_NX + Rn[1][0]*F_NY;
    float Ay = Rn[0][1]*F_NX + Rn[1][1]*F_NY;
    float Az = Rn[0][2]*F_NX + Rn[1][2]*F_NY;
    float thrA = F_THR - ((tx + g_mcf[0])*F_NX + (ty + g_mcf[1])*F_NY);
    float cx =  F_NY*wz;
    float cy = -F_NX*wz;
    float cz =  F_NX*wy - F_NY*wx;
    float Bx = Rn[0][0]*cx + Rn[1][0]*cy + Rn[2][0]*cz;
    float By = Rn[0][1]*cx + Rn[1][1]*cy + Rn[2][1]*cz;
    float Bz = Rn[0][2]*cx + Rn[1][2]*cy + Rn[2][2]*cz;
    float thrB = -(vx*F_NX + vy*F_NY);
    AB[0] = Ax; AB[1] = Ay; AB[2] = Az; AB[3] = thrA;
    AB[4] = Bx; AB[5] = By; AB[6] = Bz; AB[7] = thrB;
}

// ---------------- kernels ----------------
__global__ void zero_kernel() {
    if (threadIdx.x == 0) {
        #pragma unroll
        for (int i = 0; i < 6; i++) g_I6[i] = 0.0;
        g_sum[0] = g_sum[1] = g_sum[2] = 0.0f;
        g_cnt = 0;
        g_arrive = 0u;
        g_release = 0u;
    }
}

__global__ void inertia_kernel(const float* __restrict__ x, const float* __restrict__ mc) {
    double mcx = mc[0], mcy = mc[1], mcz = mc[2];
    double s[6] = {0, 0, 0, 0, 0, 0};
    const float4* p = (const float4*)x;
    for (int g = blockIdx.x*blockDim.x + threadIdx.x; g < NGROUPS; g += gridDim.x*blockDim.x) {
        float4 f0 = p[3*g], f1 = p[3*g + 1], f2 = p[3*g + 2];
        double vx, vy, vz;
        #define ACC(a,b,c) { vx = (double)(a)-mcx; vy = (double)(b)-mcy; vz = (double)(c)-mcz; \
            s[0] += vx*vx; s[1] += vy*vy; s[2] += vz*vz; s[3] += vx*vy; s[4] += vx*vz; s[5] += vy*vz; }
        ACC(f0.x, f0.y, f0.z)
        ACC(f0.w, f1.x, f1.y)
        ACC(f1.z, f1.w, f2.x)
        ACC(f2.y, f2.z, f2.w)
        #undef ACC
    }
    #pragma unroll
    for (int o = 16; o; o >>= 1)
        #pragma unroll
        for (int i = 0; i < 6; i++) s[i] += __shfl_down_sync(0xffffffffu, s[i], o);
    __shared__ double sm[6][BLOCK/32];
    int lane = threadIdx.x & 31, w = threadIdx.x >> 5;
    if (lane == 0)
        #pragma unroll
        for (int i = 0; i < 6; i++) sm[i][w] = s[i];
    __syncthreads();
    if (threadIdx.x == 0) {
        #pragma unroll
        for (int i = 0; i < 6; i++) {
            double t = 0;
            #pragma unroll
            for (int j = 0; j < BLOCK/32; j++) t += sm[i][j];
            atomicAdd(&g_I6[i], t);
        }
    }
}

__global__ void init_kernel(const float* mc, const float* it, const float* iq,
                            const float* iv, const float* kn, const float* mu,
                            const float* ld, const float* ad) {
    double xx = g_I6[0], yy = g_I6[1], zz = g_I6[2];
    double xy = g_I6[3], xz = g_I6[4], yz = g_I6[5];
    double tr = xx + yy + zz;
    g_If[0] = (float)(tr - xx); g_If[4] = (float)(tr - yy); g_If[8] = (float)(tr - zz);
    g_If[1] = (float)(-xy); g_If[3] = (float)(-xy);
    g_If[2] = (float)(-xz); g_If[6] = (float)(-xz);
    g_If[5] = (float)(-yz); g_If[7] = (float)(-yz);
    volatile float* S = g_S;
    for (int i = 0; i < 3; i++) {
        g_mcf[i] = mc[i];
        S[i]     = it[i];      // trans
        S[7+i]   = iv[i];      // v
        S[10+i]  = 0.0f;       // omega
    }
    float q0 = iq[0], q1 = iq[1], q2 = iq[2], q3 = iq[3];
    float qi = 1.0f / sqrtf(q0*q0 + q1*q1 + q2*q2 + q3*q3);
    S[3] = q0*qi; S[4] = q1*qi; S[5] = q2*qi; S[6] = q3*qi;
    g_kn = kn[0]; g_mu = mu[0];
    g_ld = ld[0]; g_ad = ad[0];
    g_sum[0] = g_sum[1] = g_sum[2] = 0.0f;
    g_cnt = 0;
    g_arrive = 0u;
    g_release = 0u;

    float R[3][3];
    quat_to_mat_f(S[3], S[4], S[5], S[6], R);
    store_precomp(R);
    publish_AB(R, S[0], S[1], S[7], S[8], S[10], S[11], S[12]);
}

__device__ __noinline__ void do_update(int t, float* __restrict__ out) {
    volatile float* S = g_S;
    volatile float* P = g_pre;
    volatile float* vs = g_sum;
    int num = *(volatile int*)&g_cnt;
    float s0 = vs[0], s1 = vs[1], s2 = vs[2];

    float R[3][3], Iinv[3][3];
    #pragma unroll
    for (int i = 0; i < 3; i++)
        #pragma unroll
        for (int j = 0; j < 3; j++) { R[i][j] = P[3*i+j]; Iinv[i][j] = P[9 + 3*i+j]; }

    float numf = (num > 0) ? (float)num : 1.0f;
    float inumf = 1.0f / numf;
    float ri0 = s0*inumf, ri1 = s1*inumf, ri2 = s2*inumf;

    float Ri0 = R[0][0]*ri0 + R[0][1]*ri1 + R[0][2]*ri2;
    float Ri1 = R[1][0]*ri0 + R[1][1]*ri1 + R[1][2]*ri2;
    float Ri2 = R[2][0]*ri0 + R[2][1]*ri1 + R[2][2]*ri2;

    float qw = S[3], qx = S[4], qy = S[5], qz = S[6];
    float vx = S[7], vy = S[8], vz = S[9];
    float wx = S[10], wy = S[11], wz = S[12];
    float knv = g_kn, muv = g_mu, ldv = g_ld, adv = g_ad;

    // vi = v + omega x Ri
    float vix = vx + (wy*Ri2 - wz*Ri1);
    float viy = vy + (wz*Ri0 - wx*Ri2);
    float viz = vz + (wx*Ri1 - wy*Ri0);

    float vns = vix*F_NX + viy*F_NY;           // n.z == 0
    float vnx = vns*F_NX, vny = vns*F_NY;
    float vtx = vix - vnx, vty = viy - vny, vtz = viz;
    float nvn = fabsf(vns);
    float nvt = sqrtf(vtx*vtx + vty*vty + vtz*vtz);
    float alpha = 1.0f - muv*(1.0f + knv)*(nvn/(nvt + F_EPS));
    if (alpha < 0.0f) alpha = 0.0f;
    float rx = (-knv*vnx + alpha*vtx) - vix;
    float ry = (-knv*vny + alpha*vty) - viy;
    float rz = (           alpha*vtz) - viz;

    float C[3][3] = {{0.0f, -Ri2, Ri1}, {Ri2, 0.0f, -Ri0}, {-Ri1, Ri0, 0.0f}};
    float U[3][3], M[3][3];
    mm3f(C, Iinv, U);
    mm3f(U, C, M);
    float K[3][3];
    #pragma unroll
    for (int i = 0; i < 3; i++)
        #pragma unroll
        for (int j = 0; j < 3; j++) K[i][j] = ((i == j) ? F_INVM : 0.0f) - M[i][j];
    float Kinv[3][3];
    inv3f(K, Kinv);

    float Jx = Kinv[0][0]*rx + Kinv[0][1]*ry + Kinv[0][2]*rz;
    float Jy = Kinv[1][0]*rx + Kinv[1][1]*ry + Kinv[1][2]*rz;
    float Jz = Kinv[2][0]*rx + Kinv[2][1]*ry + Kinv[2][2]*rz;

    bool hit = (num > 0);
    float dvx = hit ? Jx*F_INVM : 0.0f;
    float dvy = hit ? Jy*F_INVM : 0.0f;
    float dvz = hit ? Jz*F_INVM : 0.0f;
    float cjx = Ri1*Jz - Ri2*Jy;
    float cjy = Ri2*Jx - Ri0*Jz;
    float cjz = Ri0*Jy - Ri1*Jx;
    float dwx = hit ? (Iinv[0][0]*cjx + Iinv[0][1]*cjy + Iinv[0][2]*cjz) : 0.0f;
    float dwy = hit ? (Iinv[1][0]*cjx + Iinv[1][1]*cjy + Iinv[1][2]*cjz) : 0.0f;
    float dwz = hit ? (Iinv[2][0]*cjx + Iinv[2][1]*cjy + Iinv[2][2]*cjz) : 0.0f;

    vx = vx*ldv + dvx;
    vy = (vy - 9.8f*F_DT)*ldv + dvy;
    vz = vz*ldv + dvz;
    wx = wx*adv + dwx;
    wy = wy*adv + dwy;
    wz = wz*adv + dwz;

    float tx = S[0] + F_DT*vx;
    float ty = S[1] + F_DT*vy;
    float tz = S[2] + F_DT*vz;

    float h = 0.5f*F_DT;
    float x1 = wx*h, y1 = wy*h, z1 = wz*h;
    float nqw = qw + (-x1*qx - y1*qy - z1*qz);
    float nqx = qx + ( x1*qw + y1*qz - z1*qy);
    float nqy = qy + ( y1*qw + z1*qx - x1*qz);
    float nqz = qz + ( z1*qw + x1*qy - y1*qx);
    float qni = 1.0f / sqrtf(nqw*nqw + nqx*nqx + nqy*nqy + nqz*nqz);
    nqw *= qni; nqx *= qni; nqy *= qni; nqz *= qni;

    // ---- critical path: publish next-step constants, reset, release ----
    float Rn[3][3];
    quat_to_mat_f(nqw, nqx, nqy, nqz, Rn);
    publish_AB(Rn, tx, ty, vx, vy, wx, wy, wz);

    vs[0] = 0.0f; vs[1] = 0.0f; vs[2] = 0.0f;
    *(volatile int*)&g_cnt = 0;
    *(volatile unsigned*)&g_arrive = 0u;
    __threadfence();
    *(volatile unsigned*)&g_release = (unsigned)(t + 1);

    // ---- post-release (off critical path; ordered before this block's next arrive) ----
    S[0] = tx; S[1] = ty; S[2] = tz;
    S[3] = nqw; S[4] = nqx; S[5] = nqy; S[6] = nqz;
    S[7] = vx; S[8] = vy; S[9] = vz;
    S[10] = wx; S[11] = wy; S[12] = wz;

    out[7*t + 0] = tx;
    out[7*t + 1] = ty;
    out[7*t + 2] = tz;
    out[7*t + 3] = nqw;
    out[7*t + 4] = nqx;
    out[7*t + 5] = nqy;
    out[7*t + 6] = nqz;

    store_precomp(Rn);
}

// Persistent kernel: all TSTEPS steps inside one launch.
__global__ void __launch_bounds__(BLOCK, 3) persist_kernel(const float* __restrict__ x,
                                                           float* __restrict__ out) {
    const float4* p = (const float4*)x;
    volatile float* vAB = (volatile float*)g_AB;
    volatile unsigned* vrel = (volatile unsigned*)&g_release;
    const int base = blockIdx.x*BLOCK + threadIdx.x;

    for (int t = 0; t < TSTEPS; t++) {
        // per-step constants (L1-bypassing: written by another SM)
        float Ax = vAB[0], Ay = vAB[1], Az = vAB[2], thrA = vAB[3];
        float Bx = vAB[4], By = vAB[5], Bz = vAB[6], thrB = vAB[7];

        float sx = 0.0f, sy = 0.0f, sz = 0.0f;
        int c = 0;

        #define PROC(a,b,cc) { float pa = (a)*Ax + (b)*Ay + (cc)*Az; \
                               float pb = (a)*Bx + (b)*By + (cc)*Bz; \
                               if (pa < thrA && pb < thrB) { c++; sx += (a); sy += (b); sz += (cc); } }
        // unrolled x2 grid-stride: 6 independent LDG.128 in flight per thread
        for (int g = base; g < NGROUPS; g += 2*STRIDE) {
            float4 a0 = p[3*g], a1 = p[3*g + 1], a2 = p[3*g + 2];
            int g2 = g + STRIDE;
            float4 b0, b1, b2;
            bool ok2 = (g2 < NGROUPS);
            if (ok2) { b0 = p[3*g2]; b1 = p[3*g2 + 1]; b2 = p[3*g2 + 2]; }
            PROC(a0.x, a0.y, a0.z)
            PROC(a0.w, a1.x, a1.y)
            PROC(a1.z, a1.w, a2.x)
            PROC(a2.y, a2.z, a2.w)
            if (ok2) {
                PROC(b0.x, b0.y, b0.z)
                PROC(b0.w, b1.x, b1.y)
                PROC(b1.z, b1.w, b2.x)
                PROC(b2.y, b2.z, b2.w)
            }
        }
        #undef PROC

        // warp reduce
        #pragma unroll
        for (int o = 16; o; o >>= 1) {
            sx += __shfl_down_sync(0xffffffffu, sx, o);
            sy += __shfl_down_sync(0xffffffffu, sy, o);
            sz += __shfl_down_sync(0xffffffffu, sz, o);
            c  += __shfl_down_sync(0xffffffffu, c,  o);
        }
        __shared__ float ssx[BLOCK/32], ssy[BLOCK/32], ssz[BLOCK/32];
        __shared__ int   sc[BLOCK/32];
        int lane = threadIdx.x & 31, w = threadIdx.x >> 5;
        if (lane == 0) { ssx[w] = sx; ssy[w] = sy; ssz[w] = sz; sc[w] = c; }
        __syncthreads();

        if (threadIdx.x == 0) {
            float bx = 0, by = 0, bz = 0; int bc = 0;
            #pragma unroll
            for (int j = 0; j < BLOCK/32; j++) { bx += ssx[j]; by += ssy[j]; bz += ssz[j]; bc += sc[j]; }
            if (bc) {
                atomicAdd(&g_sum[0], bx);
                atomicAdd(&g_sum[1], by);
                atomicAdd(&g_sum[2], bz);
                atomicAdd(&g_cnt, bc);
            }
            __threadfence();
            unsigned tk = atomicAdd(&g_arrive, 1u);
            if (tk == NBP - 1u) {
                do_update(t, out);          // includes reset + release
            } else {
                while (*vrel <= (unsigned)t) { }   // tight spin: fastest wake
            }
            __threadfence();   // acquire: order constant reads after release read
        }
        __syncthreads();
    }
}

extern "C" void kernel_launch(void* const* d_in, const int* in_sizes, int n_in,
                              void* d_out, int out_size) {
    const float* x  = (const float*)d_in[0];
    const float* mc = (const float*)d_in[1];
    const float* it = (const float*)d_in[2];
    const float* iq = (const float*)d_in[3];
    const float* iv = (const float*)d_in[4];
    const float* kn = (const float*)d_in[5];
    const float* mu = (const float*)d_in[6];
    const float* ld = (const float*)d_in[7];
    const float* ad = (const float*)d_in[8];
    float* out = (float*)d_out;

    zero_kernel<<<1, 32>>>();
    inertia_kernel<<<1184, BLOCK>>>(x, mc);
    init_kernel<<<1, 1>>>(mc, it, iq, iv, kn, mu, ld, ad);
    persist_kernel<<<NBP, BLOCK>>>(x, out);
}

// round 5
// speedup vs baseline: 1.7663x; 1.7663x over previous
#include <cuda_runtime.h>
#include <math.h>

#define NV       2000000
#define NGROUPS  (NV/4)                 // 500000 groups of 4 vertices
#define BLOCK    256
#define NBP      444                    // persistent grid: 3 blocks/SM x 148 SMs
#define TSTEPS   240
#define STRIDE   (NBP*BLOCK)

#define F_DT     (1.0f/600.0f)
#define F_NX     (-0.34202014332566871291f)
#define F_NY     ( 0.93969262078590838405f)
#define F_THR    (-0.093969262078590838405f)   // -cos(slope)*0.1
#define F_EPS    1e-6f
#define F_INVM   (1.0f/2000000.0f)

// ---------------- device state ----------------
__device__ double  g_I6[6];              // fp64 sums: xx,yy,zz,xy,xz,yz
__device__ float   g_If[9];              // body-frame inertia (fp32) — const during persist
__device__ float   g_S[13];              // trans[0..2], quat[3..6], v[7..9], omega[10..12]
__device__ float   g_pre[18];            // precomputed R[0..8], Iinv[9..17] for current quat
__device__ float   g_mcf[3];
__device__ float   g_kn, g_mu, g_ld, g_ad;
__device__ float   g_AB[8];              // Ax,Ay,Az,thrA, Bx,By,Bz,thrB
__device__ float   g_sum[3];
__device__ int     g_cnt;
__device__ unsigned g_arrive;
__device__ unsigned g_release;           // number of completed steps

// ---------------- fp32 small math ----------------
__device__ __forceinline__ void quat_to_mat_f(float qw, float qx, float qy, float qz, float R[3][3]) {
    float n2 = qw*qw + qx*qx + qy*qy + qz*qz;
    float inv = 1.0f / sqrtf(n2);
    float w = qw*inv, x = qx*inv, y = qy*inv, z = qz*inv;
    R[0][0] = 1.0f - 2.0f*(y*y + z*z); R[0][1] = 2.0f*(x*y - w*z);        R[0][2] = 2.0f*(x*z + w*y);
    R[1][0] = 2.0f*(x*y + w*z);        R[1][1] = 1.0f - 2.0f*(x*x + z*z); R[1][2] = 2.0f*(y*z - w*x);
    R[2][0] = 2.0f*(x*z - w*y);        R[2][1] = 2.0f*(y*z + w*x);        R[2][2] = 1.0f - 2.0f*(x*x + y*y);
}

__device__ __forceinline__ void inv3f(const float m[3][3], float o[3][3]) {
    float c00 = m[1][1]*m[2][2] - m[1][2]*m[2][1];
    float c01 = m[1][2]*m[2][0] - m[1][0]*m[2][2];
    float c02 = m[1][0]*m[2][1] - m[1][1]*m[2][0];
    float det = m[0][0]*c00 + m[0][1]*c01 + m[0][2]*c02;
    float id = 1.0f/det;
    o[0][0] = c00*id;
    o[0][1] = (m[0][2]*m[2][1] - m[0][1]*m[2][2])*id;
    o[0][2] = (m[0][1]*m[1][2] - m[0][2]*m[1][1])*id;
    o[1][0] = c01*id;
    o[1][1] = (m[0][0]*m[2][2] - m[0][2]*m[2][0])*id;
    o[1][2] = (m[0][2]*m[1][0] - m[0][0]*m[1][2])*id;
    o[2][0] = c02*id;
    o[2][1] = (m[0][1]*m[2][0] - m[0][0]*m[2][1])*id;
    o[2][2] = (m[0][0]*m[1][1] - m[0][1]*m[1][0])*id;
}

__device__ __forceinline__ void mm3f(const float a[3][3], const float b[3][3], float c[3][3]) {
    #pragma unroll
    for (int i = 0; i < 3; i++)
        #pragma unroll
        for (int j = 0; j < 3; j++)
            c[i][j] = a[i][0]*b[0][j] + a[i][1]*b[1][j] + a[i][2]*b[2][j];
}

__device__ __forceinline__ void store_precomp(const float R[3][3]) {
    volatile float* P = g_pre;
    float In[3][3] = {{g_If[0], g_If[1], g_If[2]},
                      {g_If[3], g_If[4], g_If[5]},
                      {g_If[6], g_If[7], g_If[8]}};
    float Tm[3][3], Rt[3][3], Iw[3][3], Iinv[3][3];
    mm3f(R, In, Tm);
    #pragma unroll
    for (int i = 0; i < 3; i++)
        #pragma unroll
        for (int j = 0; j < 3; j++) Rt[i][j] = R[j][i];
    mm3f(Tm, Rt, Iw);
    inv3f(Iw, Iinv);
    #pragma unroll
    for (int i = 0; i < 3; i++)
        #pragma unroll
        for (int j = 0; j < 3; j++) { P[3*i+j] = R[i][j]; P[9 + 3*i+j] = Iinv[i][j]; }
}

__device__ __forceinline__ void publish_AB(const float Rn[3][3],
                                           float tx, float ty,
                                           float vx, float vy,
                                           float wx, float wy, float wz) {
    volatile float* AB = g_AB;
    float Ax = Rn[0][0]*F_NX + Rn[1][0]*F_NY;
    float Ay = Rn[0][1]*F_NX + Rn[1][1]*F_NY;
    float Az = Rn[0][2]*F_NX + Rn[1][2]*F_NY;
    float thrA = F_THR - ((tx + g_mcf[0])*F_NX + (ty + g_mcf[1])*F_NY);
    float cx =  F_NY*wz;
    float cy = -F_NX*wz;
    float cz =  F_NX*wy - F_NY*wx;
    float Bx = Rn[0][0]*cx + Rn[1][0]*cy + Rn[2][0]*cz;
    float By = Rn[0][1]*cx + Rn[1][1]*cy + Rn[2][1]*cz;
    float Bz = Rn[0][2]*cx + Rn[1][2]*cy + Rn[2][2]*cz;
    float thrB = -(vx*F_NX + vy*F_NY);
    AB[0] = Ax; AB[1] = Ay; AB[2] = Az; AB[3] = thrA;
    AB[4] = Bx; AB[5] = By; AB[6] = Bz; AB[7] = thrB;
}

// ---------------- kernels ----------------
__global__ void zero_kernel() {
    if (threadIdx.x == 0) {
        #pragma unroll
        for (int i = 0; i < 6; i++) g_I6[i] = 0.0;
        g_sum[0] = g_sum[1] = g_sum[2] = 0.0f;
        g_cnt = 0;
        g_arrive = 0u;
        g_release = 0u;
    }
}

__global__ void inertia_kernel(const float* __restrict__ x, const float* __restrict__ mc) {
    double mcx = mc[0], mcy = mc[1], mcz = mc[2];
    double s[6] = {0, 0, 0, 0, 0, 0};
    const float4* p = (const float4*)x;
    for (int g = blockIdx.x*blockDim.x + threadIdx.x; g < NGROUPS; g += gridDim.x*blockDim.x) {
        float4 f0 = p[3*g], f1 = p[3*g + 1], f2 = p[3*g + 2];
        double vx, vy, vz;
        #define ACC(a,b,c) { vx = (double)(a)-mcx; vy = (double)(b)-mcy; vz = (double)(c)-mcz; \
            s[0] += vx*vx; s[1] += vy*vy; s[2] += vz*vz; s[3] += vx*vy; s[4] += vx*vz; s[5] += vy*vz; }
        ACC(f0.x, f0.y, f0.z)
        ACC(f0.w, f1.x, f1.y)
        ACC(f1.z, f1.w, f2.x)
        ACC(f2.y, f2.z, f2.w)
        #undef ACC
    }
    #pragma unroll
    for (int o = 16; o; o >>= 1)
        #pragma unroll
        for (int i = 0; i < 6; i++) s[i] += __shfl_down_sync(0xffffffffu, s[i], o);
    __shared__ double sm[6][BLOCK/32];
    int lane = threadIdx.x & 31, w = threadIdx.x >> 5;
    if (lane == 0)
        #pragma unroll
        for (int i = 0; i < 6; i++) sm[i][w] = s[i];
    __syncthreads();
    if (threadIdx.x == 0) {
        #pragma unroll
        for (int i = 0; i < 6; i++) {
            double t = 0;
            #pragma unroll
            for (int j = 0; j < BLOCK/32; j++) t += sm[i][j];
            atomicAdd(&g_I6[i], t);
        }
    }
}

__global__ void init_kernel(const float* mc, const float* it, const float* iq,
                            const float* iv, const float* kn, const float* mu,
                            const float* ld, const float* ad) {
    double xx = g_I6[0], yy = g_I6[1], zz = g_I6[2];
    double xy = g_I6[3], xz = g_I6[4], yz = g_I6[5];
    double tr = xx + yy + zz;
    g_If[0] = (float)(tr - xx); g_If[4] = (float)(tr - yy); g_If[8] = (float)(tr - zz);
    g_If[1] = (float)(-xy); g_If[3] = (float)(-xy);
    g_If[2] = (float)(-xz); g_If[6] = (float)(-xz);
    g_If[5] = (float)(-yz); g_If[7] = (float)(-yz);
    volatile float* S = g_S;
    for (int i = 0; i < 3; i++) {
        g_mcf[i] = mc[i];
        S[i]     = it[i];      // trans
        S[7+i]   = iv[i];      // v
        S[10+i]  = 0.0f;       // omega
    }
    float q0 = iq[0], q1 = iq[1], q2 = iq[2], q3 = iq[3];
    float qi = 1.0f / sqrtf(q0*q0 + q1*q1 + q2*q2 + q3*q3);
    S[3] = q0*qi; S[4] = q1*qi; S[5] = q2*qi; S[6] = q3*qi;
    g_kn = kn[0]; g_mu = mu[0];
    g_ld = ld[0]; g_ad = ad[0];
    g_sum[0] = g_sum[1] = g_sum[2] = 0.0f;
    g_cnt = 0;
    g_arrive = 0u;
    g_release = 0u;

    float R[3][3];
    quat_to_mat_f(S[3], S[4], S[5], S[6], R);
    store_precomp(R);
    publish_AB(R, S[0], S[1], S[7], S[8], S[10], S[11], S[12]);
}

__device__ __noinline__ void do_update(int t, float* __restrict__ out) {
    volatile float* S = g_S;
    volatile float* P = g_pre;
    volatile float* vs = g_sum;
    int num = *(volatile int*)&g_cnt;
    float s0 = vs[0], s1 = vs[1], s2 = vs[2];

    float R[3][3], Iinv[3][3];
    #pragma unroll
    for (int i = 0; i < 3; i++)
        #pragma unroll
        for (int j = 0; j < 3; j++) { R[i][j] = P[3*i+j]; Iinv[i][j] = P[9 + 3*i+j]; }

    float numf = (num > 0) ? (float)num : 1.0f;
    float inumf = 1.0f / numf;
    float ri0 = s0*inumf, ri1 = s1*inumf, ri2 = s2*inumf;

    float Ri0 = R[0][0]*ri0 + R[0][1]*ri1 + R[0][2]*ri2;
    float Ri1 = R[1][0]*ri0 + R[1][1]*ri1 + R[1][2]*ri2;
    float Ri2 = R[2][0]*ri0 + R[2][1]*ri1 + R[2][2]*ri2;

    float qw = S[3], qx = S[4], qy = S[5], qz = S[6];
    float vx = S[7], vy = S[8], vz = S[9];
    float wx = S[10], wy = S[11], wz = S[12];
    float knv = g_kn, muv = g_mu, ldv = g_ld, adv = g_ad;

    float vix = vx + (wy*Ri2 - wz*Ri1);
    float viy = vy + (wz*Ri0 - wx*Ri2);
    float viz = vz + (wx*Ri1 - wy*Ri0);

    float vns = vix*F_NX + viy*F_NY;
    float vnx = vns*F_NX, vny = vns*F_NY;
    float vtx = vix - vnx, vty = viy - vny, vtz = viz;
    float nvn = fabsf(vns);
    float nvt = sqrtf(vtx*vtx + vty*vty + vtz*vtz);
    float alpha = 1.0f - muv*(1.0f + knv)*(nvn/(nvt + F_EPS));
    if (alpha < 0.0f) alpha = 0.0f;
    float rx = (-knv*vnx + alpha*vtx) - vix;
    float ry = (-knv*vny + alpha*vty) - viy;
    float rz = (           alpha*vtz) - viz;

    float C[3][3] = {{0.0f, -Ri2, Ri1}, {Ri2, 0.0f, -Ri0}, {-Ri1, Ri0, 0.0f}};
    float U[3][3], M[3][3];
    mm3f(C, Iinv, U);
    mm3f(U, C, M);
    float K[3][3];
    #pragma unroll
    for (int i = 0; i < 3; i++)
        #pragma unroll
        for (int j = 0; j < 3; j++) K[i][j] = ((i == j) ? F_INVM : 0.0f) - M[i][j];
    float Kinv[3][3];
    inv3f(K, Kinv);

    float Jx = Kinv[0][0]*rx + Kinv[0][1]*ry + Kinv[0][2]*rz;
    float Jy = Kinv[1][0]*rx + Kinv[1][1]*ry + Kinv[1][2]*rz;
    float Jz = Kinv[2][0]*rx + Kinv[2][1]*ry + Kinv[2][2]*rz;

    bool hit = (num > 0);
    float dvx = hit ? Jx*F_INVM : 0.0f;
    float dvy = hit ? Jy*F_INVM : 0.0f;
    float dvz = hit ? Jz*F_INVM : 0.0f;
    float cjx = Ri1*Jz - Ri2*Jy;
    float cjy = Ri2*Jx - Ri0*Jz;
    float cjz = Ri0*Jy - Ri1*Jx;
    float dwx = hit ? (Iinv[0][0]*cjx + Iinv[0][1]*cjy + Iinv[0][2]*cjz) : 0.0f;
    float dwy = hit ? (Iinv[1][0]*cjx + Iinv[1][1]*cjy + Iinv[1][2]*cjz) : 0.0f;
    float dwz = hit ? (Iinv[2][0]*cjx + Iinv[2][1]*cjy + Iinv[2][2]*cjz) : 0.0f;

    vx = vx*ldv + dvx;
    vy = (vy - 9.8f*F_DT)*ldv + dvy;
    vz = vz*ldv + dvz;
    wx = wx*adv + dwx;
    wy = wy*adv + dwy;
    wz = wz*adv + dwz;

    float tx = S[0] + F_DT*vx;
    float ty = S[1] + F_DT*vy;
    float tz = S[2] + F_DT*vz;

    float h = 0.5f*F_DT;
    float x1 = wx*h, y1 = wy*h, z1 = wz*h;
    float nqw = qw + (-x1*qx - y1*qy - z1*qz);
    float nqx = qx + ( x1*qw + y1*qz - z1*qy);
    float nqy = qy + ( y1*qw + z1*qx - x1*qz);
    float nqz = qz + ( z1*qw + x1*qy - y1*qx);
    float qni = 1.0f / sqrtf(nqw*nqw + nqx*nqx + nqy*nqy + nqz*nqz);
    nqw *= qni; nqx *= qni; nqy *= qni; nqz *= qni;

    // ---- critical path: publish next-step constants, reset, release ----
    float Rn[3][3];
    quat_to_mat_f(nqw, nqx, nqy, nqz, Rn);
    publish_AB(Rn, tx, ty, vx, vy, wx, wy, wz);

    vs[0] = 0.0f; vs[1] = 0.0f; vs[2] = 0.0f;
    *(volatile int*)&g_cnt = 0;
    *(volatile unsigned*)&g_arrive = 0u;
    __threadfence();
    *(volatile unsigned*)&g_release = (unsigned)(t + 1);

    // ---- post-release (off critical path; ordered before this block's next arrive) ----
    S[0] = tx; S[1] = ty; S[2] = tz;
    S[3] = nqw; S[4] = nqx; S[5] = nqy; S[6] = nqz;
    S[7] = vx; S[8] = vy; S[9] = vz;
    S[10] = wx; S[11] = wy; S[12] = wz;

    out[7*t + 0] = tx;
    out[7*t + 1] = ty;
    out[7*t + 2] = tz;
    out[7*t + 3] = nqw;
    out[7*t + 4] = nqx;
    out[7*t + 5] = nqy;
    out[7*t + 6] = nqz;

    store_precomp(Rn);
}

// Persistent kernel: all TSTEPS steps inside one launch.
__global__ void __launch_bounds__(BLOCK, 3) persist_kernel(const float* __restrict__ x,
                                                           float* __restrict__ out) {
    const float4* p = (const float4*)x;
    volatile float* vAB = (volatile float*)g_AB;
    volatile unsigned* vrel = (volatile unsigned*)&g_release;
    const int base = blockIdx.x*BLOCK + threadIdx.x;

    __shared__ float sAB[8];                 // block-local constants for current step
    __shared__ float ssx[BLOCK/32], ssy[BLOCK/32], ssz[BLOCK/32];
    __shared__ int   sc[BLOCK/32];

    // preload step-0 constants (init_kernel published them before we launched)
    if (threadIdx.x == 0) {
        #pragma unroll
        for (int i = 0; i < 8; i++) sAB[i] = vAB[i];
    }
    __syncthreads();

    for (int t = 0; t < TSTEPS; t++) {
        // per-step constants from shared memory (one L2 reader per block)
        float Ax = sAB[0], Ay = sAB[1], Az = sAB[2], thrA = sAB[3];
        float Bx = sAB[4], By = sAB[5], Bz = sAB[6], thrB = sAB[7];

        float sx = 0.0f, sy = 0.0f, sz = 0.0f;
        int c = 0;

        #define PROC(a,b,cc) { float pa = (a)*Ax + (b)*Ay + (cc)*Az; \
                               float pb = (a)*Bx + (b)*By + (cc)*Bz; \
                               if (pa < thrA && pb < thrB) { c++; sx += (a); sy += (b); sz += (cc); } }
        for (int g = base; g < NGROUPS; g += 2*STRIDE) {
            float4 a0 = p[3*g], a1 = p[3*g + 1], a2 = p[3*g + 2];
            int g2 = g + STRIDE;
            float4 b0, b1, b2;
            bool ok2 = (g2 < NGROUPS);
            if (ok2) { b0 = p[3*g2]; b1 = p[3*g2 + 1]; b2 = p[3*g2 + 2]; }
            PROC(a0.x, a0.y, a0.z)
            PROC(a0.w, a1.x, a1.y)
            PROC(a1.z, a1.w, a2.x)
            PROC(a2.y, a2.z, a2.w)
            if (ok2) {
                PROC(b0.x, b0.y, b0.z)
                PROC(b0.w, b1.x, b1.y)
                PROC(b1.z, b1.w, b2.x)
                PROC(b2.y, b2.z, b2.w)
            }
        }
        #undef PROC

        // warp reduce
        #pragma unroll
        for (int o = 16; o; o >>= 1) {
            sx += __shfl_down_sync(0xffffffffu, sx, o);
            sy += __shfl_down_sync(0xffffffffu, sy, o);
            sz += __shfl_down_sync(0xffffffffu, sz, o);
            c  += __shfl_down_sync(0xffffffffu, c,  o);
        }
        int lane = threadIdx.x & 31, w = threadIdx.x >> 5;
        if (lane == 0) { ssx[w] = sx; ssy[w] = sy; ssz[w] = sz; sc[w] = c; }
        __syncthreads();

        if (threadIdx.x == 0) {
            float bx = 0, by = 0, bz = 0; int bc = 0;
            #pragma unroll
            for (int j = 0; j < BLOCK/32; j++) { bx += ssx[j]; by += ssy[j]; bz += ssz[j]; bc += sc[j]; }
            if (bc) {
                atomicAdd(&g_sum[0], bx);
                atomicAdd(&g_sum[1], by);
                atomicAdd(&g_sum[2], bz);
                atomicAdd(&g_cnt, bc);
            }
            __threadfence();
            unsigned tk = atomicAdd(&g_arrive, 1u);
            if (tk == NBP - 1u) {
                do_update(t, out);          // includes reset + release
            } else {
                while (*vrel <= (unsigned)t) { __nanosleep(32); }
            }
            __threadfence();                // acquire
            // fetch next-step constants once per block into smem
            #pragma unroll
            for (int i = 0; i < 8; i++) sAB[i] = vAB[i];
        }
        __syncthreads();
    }
}

extern "C" void kernel_launch(void* const* d_in, const int* in_sizes, int n_in,
                              void* d_out, int out_size) {
    const float* x  = (const float*)d_in[0];
    const float* mc = (const float*)d_in[1];
    const float* it = (const float*)d_in[2];
    const float* iq = (const float*)d_in[3];
    const float* iv = (const float*)d_in[4];
    const float* kn = (const float*)d_in[5];
    const float* mu = (const float*)d_in[6];
    const float* ld = (const float*)d_in[7];
    const float* ad = (const float*)d_in[8];
    float* out = (float*)d_out;

    zero_kernel<<<1, 32>>>();
    inertia_kernel<<<1184, BLOCK>>>(x, mc);
    init_kernel<<<1, 1>>>(mc, it, iq, iv, kn, mu, ld, ad);
    persist_kernel<<<NBP, BLOCK>>>(x, out);
}

// round 6
// speedup vs baseline: 2.2157x; 1.2544x over previous
#include <cuda_runtime.h>
#include <math.h>

#define NV       2000000
#define NGROUPS  (NV/4)                 // 500000 groups of 4 vertices
#define BLOCK    512
#define NBP      148                    // persistent grid: 1 block/SM
#define TSTEPS   240
#define STRIDE   (NBP*BLOCK)
#define NRLINES  32                     // release fan-out lines
#define RLSTRIDE 32                     // uints per line (128B)

#define IBLOCK   256                    // inertia kernel block size

#define F_DT     (1.0f/600.0f)
#define F_NX     (-0.34202014332566871291f)
#define F_NY     ( 0.93969262078590838405f)
#define F_THR    (-0.093969262078590838405f)   // -cos(slope)*0.1
#define F_EPS    1e-6f
#define F_INVM   (1.0f/2000000.0f)

// ---------------- device state ----------------
__device__ double  g_I6[6];              // fp64 sums: xx,yy,zz,xy,xz,yz
__device__ float   g_If[9];              // body-frame inertia (fp32) — const during persist
__device__ float   g_S[13];              // trans[0..2], quat[3..6], v[7..9], omega[10..12]
__device__ float   g_pre[18];            // precomputed R[0..8], Iinv[9..17] for current quat
__device__ float   g_mcf[3];
__device__ float   g_kn, g_mu, g_ld, g_ad;
__device__ float   g_AB[8];              // Ax,Ay,Az,thrA, Bx,By,Bz,thrB
__device__ float   g_sum[3];
__device__ int     g_cnt;
__device__ unsigned g_arrive;
__device__ unsigned g_rel[NRLINES*RLSTRIDE];   // fan-out release: 32 lines, 128B apart

// ---------------- fp32 small math ----------------
__device__ __forceinline__ void quat_to_mat_f(float qw, float qx, float qy, float qz, float R[3][3]) {
    float n2 = qw*qw + qx*qx + qy*qy + qz*qz;
    float inv = 1.0f / sqrtf(n2);
    float w = qw*inv, x = qx*inv, y = qy*inv, z = qz*inv;
    R[0][0] = 1.0f - 2.0f*(y*y + z*z); R[0][1] = 2.0f*(x*y - w*z);        R[0][2] = 2.0f*(x*z + w*y);
    R[1][0] = 2.0f*(x*y + w*z);        R[1][1] = 1.0f - 2.0f*(x*x + z*z); R[1][2] = 2.0f*(y*z - w*x);
    R[2][0] = 2.0f*(x*z - w*y);        R[2][1] = 2.0f*(y*z + w*x);        R[2][2] = 1.0f - 2.0f*(x*x + y*y);
}

__device__ __forceinline__ void inv3f(const float m[3][3], float o[3][3]) {
    float c00 = m[1][1]*m[2][2] - m[1][2]*m[2][1];
    float c01 = m[1][2]*m[2][0] - m[1][0]*m[2][2];
    float c02 = m[1][0]*m[2][1] - m[1][1]*m[2][0];
    float det = m[0][0]*c00 + m[0][1]*c01 + m[0][2]*c02;
    float id = 1.0f/det;
    o[0][0] = c00*id;
    o[0][1] = (m[0][2]*m[2][1] - m[0][1]*m[2][2])*id;
    o[0][2] = (m[0][1]*m[1][2] - m[0][2]*m[1][1])*id;
    o[1][0] = c01*id;
    o[1][1] = (m[0][0]*m[2][2] - m[0][2]*m[2][0])*id;
    o[1][2] = (m[0][2]*m[1][0] - m[0][0]*m[1][2])*id;
    o[2][0] = c02*id;
    o[2][1] = (m[0][1]*m[2][0] - m[0][0]*m[2][1])*id;
    o[2][2] = (m[0][0]*m[1][1] - m[0][1]*m[1][0])*id;
}

__device__ __forceinline__ void mm3f(const float a[3][3], const float b[3][3], float c[3][3]) {
    #pragma unroll
    for (int i = 0; i < 3; i++)
        #pragma unroll
        for (int j = 0; j < 3; j++)
            c[i][j] = a[i][0]*b[0][j] + a[i][1]*b[1][j] + a[i][2]*b[2][j];
}

__device__ __forceinline__ void store_precomp(const float R[3][3]) {
    volatile float* P = g_pre;
    float In[3][3] = {{g_If[0], g_If[1], g_If[2]},
                      {g_If[3], g_If[4], g_If[5]},
                      {g_If[6], g_If[7], g_If[8]}};
    float Tm[3][3], Rt[3][3], Iw[3][3], Iinv[3][3];
    mm3f(R, In, Tm);
    #pragma unroll
    for (int i = 0; i < 3; i++)
        #pragma unroll
        for (int j = 0; j < 3; j++) Rt[i][j] = R[j][i];
    mm3f(Tm, Rt, Iw);
    inv3f(Iw, Iinv);
    #pragma unroll
    for (int i = 0; i < 3; i++)
        #pragma unroll
        for (int j = 0; j < 3; j++) { P[3*i+j] = R[i][j]; P[9 + 3*i+j] = Iinv[i][j]; }
}

__device__ __forceinline__ void publish_AB(const float Rn[3][3],
                                           float tx, float ty,
                                           float vx, float vy,
                                           float wx, float wy, float wz) {
    volatile float* AB = g_AB;
    float Ax = Rn[0][0]*F_NX + Rn[1][0]*F_NY;
    float Ay = Rn[0][1]*F_NX + Rn[1][1]*F_NY;
    float Az = Rn[0][2]*F_NX + Rn[1][2]*F_NY;
    float thrA = F_THR - ((tx + g_mcf[0])*F_NX + (ty + g_mcf[1])*F_NY);
    float cx =  F_NY*wz;
    float cy = -F_NX*wz;
    float cz =  F_NX*wy - F_NY*wx;
    float Bx = Rn[0][0]*cx + Rn[1][0]*cy + Rn[2][0]*cz;
    float By = Rn[0][1]*cx + Rn[1][1]*cy + Rn[2][1]*cz;
    float Bz = Rn[0][2]*cx + Rn[1][2]*cy + Rn[2][2]*cz;
    float thrB = -(vx*F_NX + vy*F_NY);
    AB[0] = Ax; AB[1] = Ay; AB[2] = Az; AB[3] = thrA;
    AB[4] = Bx; AB[5] = By; AB[6] = Bz; AB[7] = thrB;
}

// ---------------- kernels ----------------
__global__ void zero_kernel() {
    int i = threadIdx.x;
    if (i == 0) {
        #pragma unroll
        for (int k = 0; k < 6; k++) g_I6[k] = 0.0;
        g_sum[0] = g_sum[1] = g_sum[2] = 0.0f;
        g_cnt = 0;
        g_arrive = 0u;
    }
    if (i < NRLINES) g_rel[i*RLSTRIDE] = 0u;
}

__global__ void inertia_kernel(const float* __restrict__ x, const float* __restrict__ mc) {
    double mcx = mc[0], mcy = mc[1], mcz = mc[2];
    double s[6] = {0, 0, 0, 0, 0, 0};
    const float4* p = (const float4*)x;
    for (int g = blockIdx.x*blockDim.x + threadIdx.x; g < NGROUPS; g += gridDim.x*blockDim.x) {
        float4 f0 = p[3*g], f1 = p[3*g + 1], f2 = p[3*g + 2];
        double vx, vy, vz;
        #define ACC(a,b,c) { vx = (double)(a)-mcx; vy = (double)(b)-mcy; vz = (double)(c)-mcz; \
            s[0] += vx*vx; s[1] += vy*vy; s[2] += vz*vz; s[3] += vx*vy; s[4] += vx*vz; s[5] += vy*vz; }
        ACC(f0.x, f0.y, f0.z)
        ACC(f0.w, f1.x, f1.y)
        ACC(f1.z, f1.w, f2.x)
        ACC(f2.y, f2.z, f2.w)
        #undef ACC
    }
    #pragma unroll
    for (int o = 16; o; o >>= 1)
        #pragma unroll
        for (int i = 0; i < 6; i++) s[i] += __shfl_down_sync(0xffffffffu, s[i], o);
    __shared__ double sm[6][IBLOCK/32];
    int lane = threadIdx.x & 31, w = threadIdx.x >> 5;
    if (lane == 0)
        #pragma unroll
        for (int i = 0; i < 6; i++) sm[i][w] = s[i];
    __syncthreads();
    if (threadIdx.x == 0) {
        #pragma unroll
        for (int i = 0; i < 6; i++) {
            double t = 0;
            #pragma unroll
            for (int j = 0; j < IBLOCK/32; j++) t += sm[i][j];
            atomicAdd(&g_I6[i], t);
        }
    }
}

__global__ void init_kernel(const float* mc, const float* it, const float* iq,
                            const float* iv, const float* kn, const float* mu,
                            const float* ld, const float* ad) {
    double xx = g_I6[0], yy = g_I6[1], zz = g_I6[2];
    double xy = g_I6[3], xz = g_I6[4], yz = g_I6[5];
    double tr = xx + yy + zz;
    g_If[0] = (float)(tr - xx); g_If[4] = (float)(tr - yy); g_If[8] = (float)(tr - zz);
    g_If[1] = (float)(-xy); g_If[3] = (float)(-xy);
    g_If[2] = (float)(-xz); g_If[6] = (float)(-xz);
    g_If[5] = (float)(-yz); g_If[7] = (float)(-yz);
    volatile float* S = g_S;
    for (int i = 0; i < 3; i++) {
        g_mcf[i] = mc[i];
        S[i]     = it[i];      // trans
        S[7+i]   = iv[i];      // v
        S[10+i]  = 0.0f;       // omega
    }
    float q0 = iq[0], q1 = iq[1], q2 = iq[2], q3 = iq[3];
    float qi = 1.0f / sqrtf(q0*q0 + q1*q1 + q2*q2 + q3*q3);
    S[3] = q0*qi; S[4] = q1*qi; S[5] = q2*qi; S[6] = q3*qi;
    g_kn = kn[0]; g_mu = mu[0];
    g_ld = ld[0]; g_ad = ad[0];
    g_sum[0] = g_sum[1] = g_sum[2] = 0.0f;
    g_cnt = 0;
    g_arrive = 0u;

    float R[3][3];
    quat_to_mat_f(S[3], S[4], S[5], S[6], R);
    store_precomp(R);
    publish_AB(R, S[0], S[1], S[7], S[8], S[10], S[11], S[12]);
}

__device__ __noinline__ void do_update(int t, float* __restrict__ out) {
    volatile float* S = g_S;
    volatile float* P = g_pre;
    volatile float* vs = g_sum;
    int num = *(volatile int*)&g_cnt;
    float s0 = vs[0], s1 = vs[1], s2 = vs[2];

    float R[3][3], Iinv[3][3];
    #pragma unroll
    for (int i = 0; i < 3; i++)
        #pragma unroll
        for (int j = 0; j < 3; j++) { R[i][j] = P[3*i+j]; Iinv[i][j] = P[9 + 3*i+j]; }

    float numf = (num > 0) ? (float)num : 1.0f;
    float inumf = 1.0f / numf;
    float ri0 = s0*inumf, ri1 = s1*inumf, ri2 = s2*inumf;

    float Ri0 = R[0][0]*ri0 + R[0][1]*ri1 + R[0][2]*ri2;
    float Ri1 = R[1][0]*ri0 + R[1][1]*ri1 + R[1][2]*ri2;
    float Ri2 = R[2][0]*ri0 + R[2][1]*ri1 + R[2][2]*ri2;

    float qw = S[3], qx = S[4], qy = S[5], qz = S[6];
    float vx = S[7], vy = S[8], vz = S[9];
    float wx = S[10], wy = S[11], wz = S[12];
    float knv = g_kn, muv = g_mu, ldv = g_ld, adv = g_ad;

    float vix = vx + (wy*Ri2 - wz*Ri1);
    float viy = vy + (wz*Ri0 - wx*Ri2);
    float viz = vz + (wx*Ri1 - wy*Ri0);

    float vns = vix*F_NX + viy*F_NY;
    float vnx = vns*F_NX, vny = vns*F_NY;
    float vtx = vix - vnx, vty = viy - vny, vtz = viz;
    float nvn = fabsf(vns);
    float nvt = sqrtf(vtx*vtx + vty*vty + vtz*vtz);
    float alpha = 1.0f - muv*(1.0f + knv)*(nvn/(nvt + F_EPS));
    if (alpha < 0.0f) alpha = 0.0f;
    float rx = (-knv*vnx + alpha*vtx) - vix;
    float ry = (-knv*vny + alpha*vty) - viy;
    float rz = (           alpha*vtz) - viz;

    float C[3][3] = {{0.0f, -Ri2, Ri1}, {Ri2, 0.0f, -Ri0}, {-Ri1, Ri0, 0.0f}};
    float U[3][3], M[3][3];
    mm3f(C, Iinv, U);
    mm3f(U, C, M);
    float K[3][3];
    #pragma unroll
    for (int i = 0; i < 3; i++)
        #pragma unroll
        for (int j = 0; j < 3; j++) K[i][j] = ((i == j) ? F_INVM : 0.0f) - M[i][j];
    float Kinv[3][3];
    inv3f(K, Kinv);

    float Jx = Kinv[0][0]*rx + Kinv[0][1]*ry + Kinv[0][2]*rz;
    float Jy = Kinv[1][0]*rx + Kinv[1][1]*ry + Kinv[1][2]*rz;
    float Jz = Kinv[2][0]*rx + Kinv[2][1]*ry + Kinv[2][2]*rz;

    bool hit = (num > 0);
    float dvx = hit ? Jx*F_INVM : 0.0f;
    float dvy = hit ? Jy*F_INVM : 0.0f;
    float dvz = hit ? Jz*F_INVM : 0.0f;
    float cjx = Ri1*Jz - Ri2*Jy;
    float cjy = Ri2*Jx - Ri0*Jz;
    float cjz = Ri0*Jy - Ri1*Jx;
    float dwx = hit ? (Iinv[0][0]*cjx + Iinv[0][1]*cjy + Iinv[0][2]*cjz) : 0.0f;
    float dwy = hit ? (Iinv[1][0]*cjx + Iinv[1][1]*cjy + Iinv[1][2]*cjz) : 0.0f;
    float dwz = hit ? (Iinv[2][0]*cjx + Iinv[2][1]*cjy + Iinv[2][2]*cjz) : 0.0f;

    vx = vx*ldv + dvx;
    vy = (vy - 9.8f*F_DT)*ldv + dvy;
    vz = vz*ldv + dvz;
    wx = wx*adv + dwx;
    wy = wy*adv + dwy;
    wz = wz*adv + dwz;

    float tx = S[0] + F_DT*vx;
    float ty = S[1] + F_DT*vy;
    float tz = S[2] + F_DT*vz;

    float h = 0.5f*F_DT;
    float x1 = wx*h, y1 = wy*h, z1 = wz*h;
    float nqw = qw + (-x1*qx - y1*qy - z1*qz);
    float nqx = qx + ( x1*qw + y1*qz - z1*qy);
    float nqy = qy + ( y1*qw + z1*qx - x1*qz);
    float nqz = qz + ( z1*qw + x1*qy - y1*qx);
    float qni = 1.0f / sqrtf(nqw*nqw + nqx*nqx + nqy*nqy + nqz*nqz);
    nqw *= qni; nqx *= qni; nqy *= qni; nqz *= qni;

    // ---- critical path: publish next-step constants, reset, release (fan-out) ----
    float Rn[3][3];
    quat_to_mat_f(nqw, nqx, nqy, nqz, Rn);
    publish_AB(Rn, tx, ty, vx, vy, wx, wy, wz);

    vs[0] = 0.0f; vs[1] = 0.0f; vs[2] = 0.0f;
    *(volatile int*)&g_cnt = 0;
    *(volatile unsigned*)&g_arrive = 0u;
    __threadfence();
    #pragma unroll
    for (int i = 0; i < NRLINES; i++)
        *(volatile unsigned*)&g_rel[i*RLSTRIDE] = (unsigned)(t + 1);

    // ---- post-release (off critical path; ordered before this block's next arrive) ----
    S[0] = tx; S[1] = ty; S[2] = tz;
    S[3] = nqw; S[4] = nqx; S[5] = nqy; S[6] = nqz;
    S[7] = vx; S[8] = vy; S[9] = vz;
    S[10] = wx; S[11] = wy; S[12] = wz;

    out[7*t + 0] = tx;
    out[7*t + 1] = ty;
    out[7*t + 2] = tz;
    out[7*t + 3] = nqw;
    out[7*t + 4] = nqx;
    out[7*t + 5] = nqy;
    out[7*t + 6] = nqz;

    store_precomp(Rn);
}

// Persistent kernel: all TSTEPS steps inside one launch, 1 block/SM.
__global__ void __launch_bounds__(BLOCK, 1) persist_kernel(const float* __restrict__ x,
                                                           float* __restrict__ out) {
    const float4* p = (const float4*)x;
    volatile float* vAB = (volatile float*)g_AB;
    volatile unsigned* vrel = (volatile unsigned*)&g_rel[(blockIdx.x & (NRLINES-1))*RLSTRIDE];
    const int base = blockIdx.x*BLOCK + threadIdx.x;

    __shared__ float sAB[8];
    __shared__ float ssx[BLOCK/32], ssy[BLOCK/32], ssz[BLOCK/32];
    __shared__ int   sc[BLOCK/32];

    if (threadIdx.x == 0) {
        #pragma unroll
        for (int i = 0; i < 8; i++) sAB[i] = vAB[i];
    }
    __syncthreads();

    for (int t = 0; t < TSTEPS; t++) {
        float Ax = sAB[0], Ay = sAB[1], Az = sAB[2], thrA = sAB[3];
        float Bx = sAB[4], By = sAB[5], Bz = sAB[6], thrB = sAB[7];

        float sx = 0.0f, sy = 0.0f, sz = 0.0f;
        int c = 0;

        #define PROC(a,b,cc) { float pa = (a)*Ax + (b)*Ay + (cc)*Az; \
                               float pb = (a)*Bx + (b)*By + (cc)*Bz; \
                               if (pa < thrA && pb < thrB) { c++; sx += (a); sy += (b); sz += (cc); } }
        for (int g = base; g < NGROUPS; g += 2*STRIDE) {
            float4 a0 = p[3*g], a1 = p[3*g + 1], a2 = p[3*g + 2];
            int g2 = g + STRIDE;
            float4 b0, b1, b2;
            bool ok2 = (g2 < NGROUPS);
            if (ok2) { b0 = p[3*g2]; b1 = p[3*g2 + 1]; b2 = p[3*g2 + 2]; }
            PROC(a0.x, a0.y, a0.z)
            PROC(a0.w, a1.x, a1.y)
            PROC(a1.z, a1.w, a2.x)
            PROC(a2.y, a2.z, a2.w)
            if (ok2) {
                PROC(b0.x, b0.y, b0.z)
                PROC(b0.w, b1.x, b1.y)
                PROC(b1.z, b1.w, b2.x)
                PROC(b2.y, b2.z, b2.w)
            }
        }
        #undef PROC

        // warp reduce
        #pragma unroll
        for (int o = 16; o; o >>= 1) {
            sx += __shfl_down_sync(0xffffffffu, sx, o);
            sy += __shfl_down_sync(0xffffffffu, sy, o);
            sz += __shfl_down_sync(0xffffffffu, sz, o);
            c  += __shfl_down_sync(0xffffffffu, c,  o);
        }
        int lane = threadIdx.x & 31, w = threadIdx.x >> 5;
        if (lane == 0) { ssx[w] = sx; ssy[w] = sy; ssz[w] = sz; sc[w] = c; }
        __syncthreads();

        if (threadIdx.x == 0) {
            float bx = 0, by = 0, bz = 0; int bc = 0;
            #pragma unroll
            for (int j = 0; j < BLOCK/32; j++) { bx += ssx[j]; by += ssy[j]; bz += ssz[j]; bc += sc[j]; }
            if (bc) {
                atomicAdd(&g_sum[0], bx);
                atomicAdd(&g_sum[1], by);
                atomicAdd(&g_sum[2], bz);
                atomicAdd(&g_cnt, bc);
            }
            __threadfence();
            unsigned tk = atomicAdd(&g_arrive, 1u);
            if (tk == NBP - 1u) {
                do_update(t, out);          // includes reset + fan-out release
            } else {
                while (*vrel <= (unsigned)t) { }   // tight spin (SM is idle anyway)
            }
            __threadfence();                // acquire
            #pragma unroll
            for (int i = 0; i < 8; i++) sAB[i] = vAB[i];
        }
        __syncthreads();
    }
}

extern "C" void kernel_launch(void* const* d_in, const int* in_sizes, int n_in,
                              void* d_out, int out_size) {
    const float* x  = (const float*)d_in[0];
    const float* mc = (const float*)d_in[1];
    const float* it = (const float*)d_in[2];
    const float* iq = (const float*)d_in[3];
    const float* iv = (const float*)d_in[4];
    const float* kn = (const float*)d_in[5];
    const float* mu = (const float*)d_in[6];
    const float* ld = (const float*)d_in[7];
    const float* ad = (const float*)d_in[8];
    float* out = (float*)d_out;

    zero_kernel<<<1, 64>>>();
    inertia_kernel<<<1184, IBLOCK>>>(x, mc);
    init_kernel<<<1, 1>>>(mc, it, iq, iv, kn, mu, ld, ad);
    persist_kernel<<<NBP, BLOCK>>>(x, out);
}

// round 7
// speedup vs baseline: 2.8771x; 1.2985x over previous
#include <cuda_runtime.h>
#include <math.h>

#define NV       2000000
#define NGROUPS  (NV/4)                 // 500000 groups of 4 vertices
#define BLOCK    512
#define NBP      148                    // persistent grid: 1 block/SM
#define TSTEPS   240
#define STRIDE   (NBP*BLOCK)

#define IBLOCK   256                    // inertia kernel block size

#define F_DT     (1.0f/600.0f)
#define F_NX     (-0.34202014332566871291f)
#define F_NY     ( 0.93969262078590838405f)
#define F_THR    (-0.093969262078590838405f)   // -cos(slope)*0.1
#define F_EPS    1e-6f
#define F_INVM   (1.0f/2000000.0f)

// ---------------- device state ----------------
__device__ double  g_I6[6];              // fp64 sums: xx,yy,zz,xy,xz,yz
__device__ float   g_If[9];              // body-frame inertia (fp32)
__device__ float   g_S[13];              // initial: trans[0..2], quat[3..6], v[7..9], omega[10..12]
__device__ float   g_mcf[3];
__device__ float   g_kn, g_mu, g_ld, g_ad;
__device__ float   g_AB[8];              // initial step-0 constants
__device__ float4  g_part[2][NBP];       // per-block partials, double-buffered
__device__ unsigned g_arrive;            // cumulative arrival counter (never reset)

// ---------------- fp32 small math ----------------
__device__ __forceinline__ void quat_to_mat_f(float qw, float qx, float qy, float qz, float R[3][3]) {
    float n2 = qw*qw + qx*qx + qy*qy + qz*qz;
    float inv = 1.0f / sqrtf(n2);
    float w = qw*inv, x = qx*inv, y = qy*inv, z = qz*inv;
    R[0][0] = 1.0f - 2.0f*(y*y + z*z); R[0][1] = 2.0f*(x*y - w*z);        R[0][2] = 2.0f*(x*z + w*y);
    R[1][0] = 2.0f*(x*y + w*z);        R[1][1] = 1.0f - 2.0f*(x*x + z*z); R[1][2] = 2.0f*(y*z - w*x);
    R[2][0] = 2.0f*(x*z - w*y);        R[2][1] = 2.0f*(y*z + w*x);        R[2][2] = 1.0f - 2.0f*(x*x + y*y);
}

__device__ __forceinline__ void inv3f(const float m[3][3], float o[3][3]) {
    float c00 = m[1][1]*m[2][2] - m[1][2]*m[2][1];
    float c01 = m[1][2]*m[2][0] - m[1][0]*m[2][2];
    float c02 = m[1][0]*m[2][1] - m[1][1]*m[2][0];
    float det = m[0][0]*c00 + m[0][1]*c01 + m[0][2]*c02;
    float id = 1.0f/det;
    o[0][0] = c00*id;
    o[0][1] = (m[0][2]*m[2][1] - m[0][1]*m[2][2])*id;
    o[0][2] = (m[0][1]*m[1][2] - m[0][2]*m[1][1])*id;
    o[1][0] = c01*id;
    o[1][1] = (m[0][0]*m[2][2] - m[0][2]*m[2][0])*id;
    o[1][2] = (m[0][2]*m[1][0] - m[0][0]*m[1][2])*id;
    o[2][0] = c02*id;
    o[2][1] = (m[0][1]*m[2][0] - m[0][0]*m[2][1])*id;
    o[2][2] = (m[0][0]*m[1][1] - m[0][1]*m[1][0])*id;
}

__device__ __forceinline__ void mm3f(const float a[3][3], const float b[3][3], float c[3][3]) {
    #pragma unroll
    for (int i = 0; i < 3; i++)
        #pragma unroll
        for (int j = 0; j < 3; j++)
            c[i][j] = a[i][0]*b[0][j] + a[i][1]*b[1][j] + a[i][2]*b[2][j];
}

// Iinv = inv(R * In * R^T), In symmetric given as 3x3
__device__ __forceinline__ void world_iinv(const float R[3][3], const float In[3][3], float Iinv[3][3]) {
    float Tm[3][3], Rt[3][3], Iw[3][3];
    mm3f(R, In, Tm);
    #pragma unroll
    for (int i = 0; i < 3; i++)
        #pragma unroll
        for (int j = 0; j < 3; j++) Rt[i][j] = R[j][i];
    mm3f(Tm, Rt, Iw);
    inv3f(Iw, Iinv);
}

// ---------------- kernels ----------------
__global__ void zero_kernel() {
    if (threadIdx.x == 0) {
        #pragma unroll
        for (int k = 0; k < 6; k++) g_I6[k] = 0.0;
        g_arrive = 0u;
    }
}

__global__ void inertia_kernel(const float* __restrict__ x, const float* __restrict__ mc) {
    double mcx = mc[0], mcy = mc[1], mcz = mc[2];
    double s[6] = {0, 0, 0, 0, 0, 0};
    const float4* p = (const float4*)x;
    for (int g = blockIdx.x*blockDim.x + threadIdx.x; g < NGROUPS; g += gridDim.x*blockDim.x) {
        float4 f0 = p[3*g], f1 = p[3*g + 1], f2 = p[3*g + 2];
        double vx, vy, vz;
        #define ACC(a,b,c) { vx = (double)(a)-mcx; vy = (double)(b)-mcy; vz = (double)(c)-mcz; \
            s[0] += vx*vx; s[1] += vy*vy; s[2] += vz*vz; s[3] += vx*vy; s[4] += vx*vz; s[5] += vy*vz; }
        ACC(f0.x, f0.y, f0.z)
        ACC(f0.w, f1.x, f1.y)
        ACC(f1.z, f1.w, f2.x)
        ACC(f2.y, f2.z, f2.w)
        #undef ACC
    }
    #pragma unroll
    for (int o = 16; o; o >>= 1)
        #pragma unroll
        for (int i = 0; i < 6; i++) s[i] += __shfl_down_sync(0xffffffffu, s[i], o);
    __shared__ double sm[6][IBLOCK/32];
    int lane = threadIdx.x & 31, w = threadIdx.x >> 5;
    if (lane == 0)
        #pragma unroll
        for (int i = 0; i < 6; i++) sm[i][w] = s[i];
    __syncthreads();
    if (threadIdx.x == 0) {
        #pragma unroll
        for (int i = 0; i < 6; i++) {
            double t = 0;
            #pragma unroll
            for (int j = 0; j < IBLOCK/32; j++) t += sm[i][j];
            atomicAdd(&g_I6[i], t);
        }
    }
}

__global__ void init_kernel(const float* mc, const float* it, const float* iq,
                            const float* iv, const float* kn, const float* mu,
                            const float* ld, const float* ad) {
    double xx = g_I6[0], yy = g_I6[1], zz = g_I6[2];
    double xy = g_I6[3], xz = g_I6[4], yz = g_I6[5];
    double tr = xx + yy + zz;
    g_If[0] = (float)(tr - xx); g_If[4] = (float)(tr - yy); g_If[8] = (float)(tr - zz);
    g_If[1] = (float)(-xy); g_If[3] = (float)(-xy);
    g_If[2] = (float)(-xz); g_If[6] = (float)(-xz);
    g_If[5] = (float)(-yz); g_If[7] = (float)(-yz);
    for (int i = 0; i < 3; i++) {
        g_mcf[i]  = mc[i];
        g_S[i]    = it[i];
        g_S[7+i]  = iv[i];
        g_S[10+i] = 0.0f;
    }
    float q0 = iq[0], q1 = iq[1], q2 = iq[2], q3 = iq[3];
    float qi = 1.0f / sqrtf(q0*q0 + q1*q1 + q2*q2 + q3*q3);
    g_S[3] = q0*qi; g_S[4] = q1*qi; g_S[5] = q2*qi; g_S[6] = q3*qi;
    g_kn = kn[0]; g_mu = mu[0];
    g_ld = ld[0]; g_ad = ad[0];
    g_arrive = 0u;

    // step-0 constants
    float R[3][3];
    quat_to_mat_f(g_S[3], g_S[4], g_S[5], g_S[6], R);
    float Ax = R[0][0]*F_NX + R[1][0]*F_NY;
    float Ay = R[0][1]*F_NX + R[1][1]*F_NY;
    float Az = R[0][2]*F_NX + R[1][2]*F_NY;
    float thrA = F_THR - ((g_S[0] + g_mcf[0])*F_NX + (g_S[1] + g_mcf[1])*F_NY);
    // omega = 0 -> B = 0
    g_AB[0] = Ax; g_AB[1] = Ay; g_AB[2] = Az; g_AB[3] = thrA;
    g_AB[4] = 0.0f; g_AB[5] = 0.0f; g_AB[6] = 0.0f;
    float thrB = -(g_S[7]*F_NX + g_S[8]*F_NY);
    g_AB[7] = thrB;
}

// Persistent kernel: all TSTEPS steps, 1 block/SM, fully decentralized update.
__global__ void __launch_bounds__(BLOCK, 1) persist_kernel(const float* __restrict__ x,
                                                           float* __restrict__ out) {
    const float4* p = (const float4*)x;
    const int tid = threadIdx.x;
    const int bid = blockIdx.x;
    const int base = bid*BLOCK + tid;

    __shared__ float sAB[8];
    __shared__ float sSt[13];            // trans,quat,v,omega (block-local copy of state)
    __shared__ float sR[9], sIinv[9], sInb[9];
    __shared__ float sPar[7];            // kn,mu,ld,ad, mcx,mcy,(unused)
    __shared__ float ssx[BLOCK/32], ssy[BLOCK/32], ssz[BLOCK/32], scc[BLOCK/32];
    __shared__ float gpx[5], gpy[5], gpz[5], gpc[5];   // gather partials (5 warps)

    if (tid == 0) {
        #pragma unroll
        for (int i = 0; i < 8; i++)  sAB[i] = g_AB[i];
        #pragma unroll
        for (int i = 0; i < 13; i++) sSt[i] = g_S[i];
        #pragma unroll
        for (int i = 0; i < 9; i++)  sInb[i] = g_If[i];
        sPar[0] = g_kn; sPar[1] = g_mu; sPar[2] = g_ld; sPar[3] = g_ad;
        sPar[4] = g_mcf[0]; sPar[5] = g_mcf[1];
        float R[3][3];
        quat_to_mat_f(sSt[3], sSt[4], sSt[5], sSt[6], R);
        float In[3][3] = {{sInb[0], sInb[1], sInb[2]},
                          {sInb[3], sInb[4], sInb[5]},
                          {sInb[6], sInb[7], sInb[8]}};
        float Iv[3][3];
        world_iinv(R, In, Iv);
        #pragma unroll
        for (int i = 0; i < 3; i++)
            #pragma unroll
            for (int j = 0; j < 3; j++) { sR[3*i+j] = R[i][j]; sIinv[3*i+j] = Iv[i][j]; }
    }
    __syncthreads();

    for (int t = 0; t < TSTEPS; t++) {
        float Ax = sAB[0], Ay = sAB[1], Az = sAB[2], thrA = sAB[3];
        float Bx = sAB[4], By = sAB[5], Bz = sAB[6], thrB = sAB[7];

        float sx = 0.0f, sy = 0.0f, sz = 0.0f, c = 0.0f;

        #define PROC(a,b,cc) { float pa = (a)*Ax + (b)*Ay + (cc)*Az; \
                               float pb = (a)*Bx + (b)*By + (cc)*Bz; \
                               if (pa < thrA && pb < thrB) { c += 1.0f; sx += (a); sy += (b); sz += (cc); } }
        for (int g = base; g < NGROUPS; g += 2*STRIDE) {
            float4 a0 = p[3*g], a1 = p[3*g + 1], a2 = p[3*g + 2];
            int g2 = g + STRIDE;
            float4 b0, b1, b2;
            bool ok2 = (g2 < NGROUPS);
            if (ok2) { b0 = p[3*g2]; b1 = p[3*g2 + 1]; b2 = p[3*g2 + 2]; }
            PROC(a0.x, a0.y, a0.z)
            PROC(a0.w, a1.x, a1.y)
            PROC(a1.z, a1.w, a2.x)
            PROC(a2.y, a2.z, a2.w)
            if (ok2) {
                PROC(b0.x, b0.y, b0.z)
                PROC(b0.w, b1.x, b1.y)
                PROC(b1.z, b1.w, b2.x)
                PROC(b2.y, b2.z, b2.w)
            }
        }
        #undef PROC

        // intra-block reduce
        #pragma unroll
        for (int o = 16; o; o >>= 1) {
            sx += __shfl_down_sync(0xffffffffu, sx, o);
            sy += __shfl_down_sync(0xffffffffu, sy, o);
            sz += __shfl_down_sync(0xffffffffu, sz, o);
            c  += __shfl_down_sync(0xffffffffu, c,  o);
        }
        int lane = tid & 31, w = tid >> 5;
        if (lane == 0) { ssx[w] = sx; ssy[w] = sy; ssz[w] = sz; scc[w] = c; }
        __syncthreads();

        if (tid == 0) {
            float bx = 0, by = 0, bz = 0, bc = 0;
            #pragma unroll
            for (int j = 0; j < BLOCK/32; j++) { bx += ssx[j]; by += ssy[j]; bz += ssz[j]; bc += scc[j]; }
            g_part[t & 1][bid] = make_float4(bx, by, bz, bc);
            __threadfence();
            atomicAdd(&g_arrive, 1u);
            unsigned target = (unsigned)(t + 1) * NBP;
            if (*(volatile unsigned*)&g_arrive < target) {
                while (*(volatile unsigned*)&g_arrive < target) { __nanosleep(16); }
            }
        }
        __syncthreads();   // everyone waits for the barrier; also orders .cv loads after poll

        // gather the 148 partials (threads 0..147, warps 0..4)
        if (tid < 160) {
            float4 pv = make_float4(0.f, 0.f, 0.f, 0.f);
            if (tid < NBP) pv = __ldcv(&g_part[t & 1][tid]);
            float px = pv.x, py = pv.y, pz = pv.z, pc = pv.w;
            #pragma unroll
            for (int o = 16; o; o >>= 1) {
                px += __shfl_down_sync(0xffffffffu, px, o);
                py += __shfl_down_sync(0xffffffffu, py, o);
                pz += __shfl_down_sync(0xffffffffu, pz, o);
                pc += __shfl_down_sync(0xffffffffu, pc, o);
            }
            if (lane == 0) { gpx[w] = px; gpy[w] = py; gpz[w] = pz; gpc[w] = pc; }
        }
        __syncthreads();

        if (tid == 0) {
            float s0 = gpx[0]+gpx[1]+gpx[2]+gpx[3]+gpx[4];
            float s1 = gpy[0]+gpy[1]+gpy[2]+gpy[3]+gpy[4];
            float s2 = gpz[0]+gpz[1]+gpz[2]+gpz[3]+gpz[4];
            float cnt = gpc[0]+gpc[1]+gpc[2]+gpc[3]+gpc[4];

            // ---- local state update (identical in every block) ----
            float numf = (cnt > 0.0f) ? cnt : 1.0f;
            float inumf = 1.0f / numf;
            float ri0 = s0*inumf, ri1 = s1*inumf, ri2 = s2*inumf;

            float Ri0 = sR[0]*ri0 + sR[1]*ri1 + sR[2]*ri2;
            float Ri1 = sR[3]*ri0 + sR[4]*ri1 + sR[5]*ri2;
            float Ri2 = sR[6]*ri0 + sR[7]*ri1 + sR[8]*ri2;

            float qw = sSt[3], qx = sSt[4], qy = sSt[5], qz = sSt[6];
            float vx = sSt[7], vy = sSt[8], vz = sSt[9];
            float wx = sSt[10], wy = sSt[11], wz = sSt[12];
            float knv = sPar[0], muv = sPar[1], ldv = sPar[2], adv = sPar[3];

            float vix = vx + (wy*Ri2 - wz*Ri1);
            float viy = vy + (wz*Ri0 - wx*Ri2);
            float viz = vz + (wx*Ri1 - wy*Ri0);

            float vns = vix*F_NX + viy*F_NY;
            float vnx = vns*F_NX, vny = vns*F_NY;
            float vtx = vix - vnx, vty = viy - vny, vtz = viz;
            float nvn = fabsf(vns);
            float nvt = sqrtf(vtx*vtx + vty*vty + vtz*vtz);
            float alpha = 1.0f - muv*(1.0f + knv)*(nvn/(nvt + F_EPS));
            if (alpha < 0.0f) alpha = 0.0f;
            float rx = (-knv*vnx + alpha*vtx) - vix;
            float ry = (-knv*vny + alpha*vty) - viy;
            float rz = (           alpha*vtz) - viz;

            float Iv[3][3] = {{sIinv[0], sIinv[1], sIinv[2]},
                              {sIinv[3], sIinv[4], sIinv[5]},
                              {sIinv[6], sIinv[7], sIinv[8]}};
            float C[3][3] = {{0.0f, -Ri2, Ri1}, {Ri2, 0.0f, -Ri0}, {-Ri1, Ri0, 0.0f}};
            float U[3][3], M[3][3];
            mm3f(C, Iv, U);
            mm3f(U, C, M);
            float K[3][3];
            #pragma unroll
            for (int i = 0; i < 3; i++)
                #pragma unroll
                for (int j = 0; j < 3; j++) K[i][j] = ((i == j) ? F_INVM : 0.0f) - M[i][j];
            float Kinv[3][3];
            inv3f(K, Kinv);

            float Jx = Kinv[0][0]*rx + Kinv[0][1]*ry + Kinv[0][2]*rz;
            float Jy = Kinv[1][0]*rx + Kinv[1][1]*ry + Kinv[1][2]*rz;
            float Jz = Kinv[2][0]*rx + Kinv[2][1]*ry + Kinv[2][2]*rz;

            bool hit = (cnt > 0.0f);
            float dvx = hit ? Jx*F_INVM : 0.0f;
            float dvy = hit ? Jy*F_INVM : 0.0f;
            float dvz = hit ? Jz*F_INVM : 0.0f;
            float cjx = Ri1*Jz - Ri2*Jy;
            float cjy = Ri2*Jx - Ri0*Jz;
            float cjz = Ri0*Jy - Ri1*Jx;
            float dwx = hit ? (Iv[0][0]*cjx + Iv[0][1]*cjy + Iv[0][2]*cjz) : 0.0f;
            float dwy = hit ? (Iv[1][0]*cjx + Iv[1][1]*cjy + Iv[1][2]*cjz) : 0.0f;
            float dwz = hit ? (Iv[2][0]*cjx + Iv[2][1]*cjy + Iv[2][2]*cjz) : 0.0f;

            vx = vx*ldv + dvx;
            vy = (vy - 9.8f*F_DT)*ldv + dvy;
            vz = vz*ldv + dvz;
            wx = wx*adv + dwx;
            wy = wy*adv + dwy;
            wz = wz*adv + dwz;

            float tx = sSt[0] + F_DT*vx;
            float ty = sSt[1] + F_DT*vy;
            float tz = sSt[2] + F_DT*vz;

            float h = 0.5f*F_DT;
            float x1 = wx*h, y1 = wy*h, z1 = wz*h;
            float nqw = qw + (-x1*qx - y1*qy - z1*qz);
            float nqx = qx + ( x1*qw + y1*qz - z1*qy);
            float nqy = qy + ( y1*qw + z1*qx - x1*qz);
            float nqz = qz + ( z1*qw + x1*qy - y1*qx);
            float qni = 1.0f / sqrtf(nqw*nqw + nqx*nqx + nqy*nqy + nqz*nqz);
            nqw *= qni; nqx *= qni; nqy *= qni; nqz *= qni;

            // next-step AB constants -> smem (releases the block)
            float Rn[3][3];
            quat_to_mat_f(nqw, nqx, nqy, nqz, Rn);
            sAB[0] = Rn[0][0]*F_NX + Rn[1][0]*F_NY;
            sAB[1] = Rn[0][1]*F_NX + Rn[1][1]*F_NY;
            sAB[2] = Rn[0][2]*F_NX + Rn[1][2]*F_NY;
            sAB[3] = F_THR - ((tx + sPar[4])*F_NX + (ty + sPar[5])*F_NY);
            float cx =  F_NY*wz;
            float cy = -F_NX*wz;
            float cz =  F_NX*wy - F_NY*wx;
            sAB[4] = Rn[0][0]*cx + Rn[1][0]*cy + Rn[2][0]*cz;
            sAB[5] = Rn[0][1]*cx + Rn[1][1]*cy + Rn[2][1]*cz;
            sAB[6] = Rn[0][2]*cx + Rn[1][2]*cy + Rn[2][2]*cz;
            sAB[7] = -(vx*F_NX + vy*F_NY);

            sSt[0] = tx;  sSt[1] = ty;  sSt[2] = tz;
            sSt[3] = nqw; sSt[4] = nqx; sSt[5] = nqy; sSt[6] = nqz;
            sSt[7] = vx;  sSt[8] = vy;  sSt[9] = vz;
            sSt[10] = wx; sSt[11] = wy; sSt[12] = wz;

            #pragma unroll
            for (int i = 0; i < 3; i++)
                #pragma unroll
                for (int j = 0; j < 3; j++) sR[3*i+j] = Rn[i][j];

            if (bid == 0) {
                out[7*t + 0] = tx;
                out[7*t + 1] = ty;
                out[7*t + 2] = tz;
                out[7*t + 3] = nqw;
                out[7*t + 4] = nqx;
                out[7*t + 5] = nqy;
                out[7*t + 6] = nqz;
            }
        }
        __syncthreads();   // all threads see new sAB; proceed to next reduce

        // off critical path: thread0 prepares Iinv for the next update while
        // the other warps already stream the next reduction.
        if (tid == 0 && t + 1 < TSTEPS) {
            float Rn[3][3] = {{sR[0], sR[1], sR[2]},
                              {sR[3], sR[4], sR[5]},
                              {sR[6], sR[7], sR[8]}};
            float In[3][3] = {{sInb[0], sInb[1], sInb[2]},
                              {sInb[3], sInb[4], sInb[5]},
                              {sInb[6], sInb[7], sInb[8]}};
            float Iv[3][3];
            world_iinv(Rn, In, Iv);
            #pragma unroll
            for (int i = 0; i < 3; i++)
                #pragma unroll
                for (int j = 0; j < 3; j++) sIinv[3*i+j] = Iv[i][j];
        }
    }
}

extern "C" void kernel_launch(void* const* d_in, const int* in_sizes, int n_in,
                              void* d_out, int out_size) {
    const float* x  = (const float*)d_in[0];
    const float* mc = (const float*)d_in[1];
    const float* it = (const float*)d_in[2];
    const float* iq = (const float*)d_in[3];
    const float* iv = (const float*)d_in[4];
    const float* kn = (const float*)d_in[5];
    const float* mu = (const float*)d_in[6];
    const float* ld = (const float*)d_in[7];
    const float* ad = (const float*)d_in[8];
    float* out = (float*)d_out;

    zero_kernel<<<1, 32>>>();
    inertia_kernel<<<1184, IBLOCK>>>(x, mc);
    init_kernel<<<1, 1>>>(mc, it, iq, iv, kn, mu, ld, ad);
    persist_kernel<<<NBP, BLOCK>>>(x, out);
}